// round 7
// baseline (speedup 1.0000x reference)
#include <cuda_runtime.h>

// LeadLagSignature depth-3 via sliding-window Chen recursion.
// Block handles CHUNK consecutive positions: full 15-diff recursion for the
// first, then per position one combined left-removal (C = e^{-G} ⊗ e^{-L})
// plus the usual right-append of the two new increments.
// Thread (a, b) owns S2/S3 row a, columns b and b+8. 128 threads/block.

#define DIM 8
#define PATCH 16
#define NDIFF 15
#define LLD 16
#define CHUNK 8
#define NDT (NDIFF + CHUNK - 1)   // 22 diffs per block

typedef unsigned long long u64;

__device__ __forceinline__ u64 ffma2(u64 a, u64 b, u64 c) {
    u64 d;
    asm("fma.rn.f32x2 %0, %1, %2, %3;" : "=l"(d) : "l"(a), "l"(b), "l"(c));
    return d;
}

__device__ __forceinline__ u64 bcast2(float f) {
    unsigned int r = __float_as_uint(f);
    u64 d;
    asm("mov.b64 %0, {%1, %1};" : "=l"(d) : "r"(r));
    return d;
}

// Right-append of the two increments (lead then lag) of one diff vector dv.
// ALEAD: row a in lead half (warp-uniform).
template <bool ALEAD>
__device__ __forceinline__ void right_pair(const float* __restrict__ dv,
                                           int ai, int bi,
                                           u64* s3b, u64* s3g,
                                           float& s2b, float& s2g, float& s1a)
{
    const float C2 = 0.5f;
    const float C3 = 1.0f / 6.0f;
    const ulonglong2 pA = *reinterpret_cast<const ulonglong2*>(dv);
    const ulonglong2 pB = *reinterpret_cast<const ulonglong2*>(dv + 4);
    const float va = dv[ai];
    const float vb = dv[bi];

    float Fb, F2b, Fg, F2g;
    if (ALEAD) {
        Fg = s2g;
        const float cs1 = C2 * s1a;
        const float u   = fmaf(C3, va, cs1);
        Fb  = fmaf(vb, u, s2b);
        const float w   = fmaf(C2, va, s1a);
        s2b = fmaf(vb, w, s2b);
        s1a += va;
        F2b = s2b;
        const float h   = C2 * s1a;
        F2g = fmaf(vb, h, s2g);
        s2g = fmaf(vb, s1a, s2g);
    } else {
        const float cs1 = C2 * s1a;
        Fb  = fmaf(vb, cs1, s2b);
        s2b = fmaf(vb, s1a, s2b);
        Fg  = s2g;
        F2b = s2b;
        const float u   = fmaf(C3, va, cs1);
        F2g = fmaf(vb, u, s2g);
        const float w   = fmaf(C2, va, s1a);
        s2g = fmaf(vb, w, s2g);
        s1a += va;
    }

    const u64 Fbp  = bcast2(Fb);
    const u64 F2bp = bcast2(F2b);
    const u64 Fgp  = bcast2(Fg);
    const u64 F2gp = bcast2(F2g);

    s3b[0] = ffma2(Fbp,  pA.x, s3b[0]);
    s3b[1] = ffma2(Fbp,  pA.y, s3b[1]);
    s3b[2] = ffma2(Fbp,  pB.x, s3b[2]);
    s3b[3] = ffma2(Fbp,  pB.y, s3b[3]);
    s3b[4] = ffma2(F2bp, pA.x, s3b[4]);
    s3b[5] = ffma2(F2bp, pA.y, s3b[5]);
    s3b[6] = ffma2(F2bp, pB.x, s3b[6]);
    s3b[7] = ffma2(F2bp, pB.y, s3b[7]);
    s3g[0] = ffma2(Fgp,  pA.x, s3g[0]);
    s3g[1] = ffma2(Fgp,  pA.y, s3g[1]);
    s3g[2] = ffma2(Fgp,  pB.x, s3g[2]);
    s3g[3] = ffma2(Fgp,  pB.y, s3g[3]);
    s3g[4] = ffma2(F2gp, pA.x, s3g[4]);
    s3g[5] = ffma2(F2gp, pA.y, s3g[5]);
    s3g[6] = ffma2(F2gp, pB.x, s3g[6]);
    s3g[7] = ffma2(F2gp, pB.y, s3g[7]);
}

// Combined left-removal by C = e^{-G(d)} ⊗ e^{-L(d)}:
//   S1'      = S1 - vfull
//   S2'[a,c] = S2[a,c] - Da*S1[c] + m2(a,c)*Da*Dc
//   S3'[a,c,:] += C1[a]*S2old[c,:] + C2[a,c]*S1old[:] + C3[a,c,:]
// with m2 = {same half: 1/2, a lag & c lead: 1, a lead & c lag: 0} and
// C3[a,c,e] = -Da*Dc*De * m3, m3 nonzero iff h(a)>=h(c)>=h(e):
//   (0,0,0)=1/6, (1,1,1)=1/6, (1,0,0)=1/2, (1,1,0)=1/2.
template <bool ALEAD>
__device__ __forceinline__ void left_remove(const float* __restrict__ dOld,
                                            const float* __restrict__ s2rowb,
                                            const float* __restrict__ s2rowg,
                                            const float* __restrict__ s1old,
                                            int ai, int b,
                                            u64* s3b, u64* s3g,
                                            float& s2b, float& s2g, float& s1a)
{
    const float Da = dOld[ai];
    const float Db = dOld[b];           // note: Δ_{b+8} == Δ_b
    const ulonglong2 v0 = *reinterpret_cast<const ulonglong2*>(dOld);
    const ulonglong2 v1 = *reinterpret_cast<const ulonglong2*>(dOld + 4);
    const u64 C1 = bcast2(-Da);
    const float t = Da * Db;

    const ulonglong2 q0 = *reinterpret_cast<const ulonglong2*>(s1old);
    const ulonglong2 q1 = *reinterpret_cast<const ulonglong2*>(s1old + 4);
    const ulonglong2 q2 = *reinterpret_cast<const ulonglong2*>(s1old + 8);
    const ulonglong2 q3 = *reinterpret_cast<const ulonglong2*>(s1old + 12);
    const float S1b  = s1old[b];
    const float S1b8 = s1old[b + 8];

    const ulonglong2 rb0 = *reinterpret_cast<const ulonglong2*>(s2rowb);
    const ulonglong2 rb1 = *reinterpret_cast<const ulonglong2*>(s2rowb + 4);
    const ulonglong2 rb2 = *reinterpret_cast<const ulonglong2*>(s2rowb + 8);
    const ulonglong2 rb3 = *reinterpret_cast<const ulonglong2*>(s2rowb + 12);
    const ulonglong2 rg0 = *reinterpret_cast<const ulonglong2*>(s2rowg);
    const ulonglong2 rg1 = *reinterpret_cast<const ulonglong2*>(s2rowg + 4);
    const ulonglong2 rg2 = *reinterpret_cast<const ulonglong2*>(s2rowg + 8);
    const ulonglong2 rg3 = *reinterpret_cast<const ulonglong2*>(s2rowg + 12);

    // C1 ⊗ S2old term — both columns, all c-pairs
    s3b[0] = ffma2(C1, rb0.x, s3b[0]);
    s3b[1] = ffma2(C1, rb0.y, s3b[1]);
    s3b[2] = ffma2(C1, rb1.x, s3b[2]);
    s3b[3] = ffma2(C1, rb1.y, s3b[3]);
    s3b[4] = ffma2(C1, rb2.x, s3b[4]);
    s3b[5] = ffma2(C1, rb2.y, s3b[5]);
    s3b[6] = ffma2(C1, rb3.x, s3b[6]);
    s3b[7] = ffma2(C1, rb3.y, s3b[7]);
    s3g[0] = ffma2(C1, rg0.x, s3g[0]);
    s3g[1] = ffma2(C1, rg0.y, s3g[1]);
    s3g[2] = ffma2(C1, rg1.x, s3g[2]);
    s3g[3] = ffma2(C1, rg1.y, s3g[3]);
    s3g[4] = ffma2(C1, rg2.x, s3g[4]);
    s3g[5] = ffma2(C1, rg2.y, s3g[5]);
    s3g[6] = ffma2(C1, rg3.x, s3g[6]);
    s3g[7] = ffma2(C1, rg3.y, s3g[7]);

    if (ALEAD) {
        // col b (lead): C2 = t/2, K3(lead c) = -t/6, K3(lag c) = 0
        // col b+8 (lag): C2 = 0, K3 = 0 (h(a) < h(col))
        const u64 C2b = bcast2(0.5f * t);
        const u64 K3l = bcast2(-t * (1.0f / 6.0f));
        s3b[0] = ffma2(C2b, q0.x, s3b[0]);
        s3b[1] = ffma2(C2b, q0.y, s3b[1]);
        s3b[2] = ffma2(C2b, q1.x, s3b[2]);
        s3b[3] = ffma2(C2b, q1.y, s3b[3]);
        s3b[4] = ffma2(C2b, q2.x, s3b[4]);
        s3b[5] = ffma2(C2b, q2.y, s3b[5]);
        s3b[6] = ffma2(C2b, q3.x, s3b[6]);
        s3b[7] = ffma2(C2b, q3.y, s3b[7]);
        s3b[0] = ffma2(K3l, v0.x, s3b[0]);
        s3b[1] = ffma2(K3l, v0.y, s3b[1]);
        s3b[2] = ffma2(K3l, v1.x, s3b[2]);
        s3b[3] = ffma2(K3l, v1.y, s3b[3]);
        s2b = fmaf(-Da, S1b, fmaf(0.5f * Da, Db, s2b));
        s2g = fmaf(-Da, S1b8, s2g);
    } else {
        // col b (lead): C2 = t (m2(1,0)=1), K3(lead c) = -t/2, K3(lag c) = 0
        // col b+8 (lag): C2 = t/2, K3(lead c) = -t/2, K3(lag c) = -t/6
        const u64 C2b = bcast2(t);
        const u64 C2g = bcast2(0.5f * t);
        const u64 K3h = bcast2(-0.5f * t);
        const u64 K36 = bcast2(-t * (1.0f / 6.0f));
        s3b[0] = ffma2(C2b, q0.x, s3b[0]);
        s3b[1] = ffma2(C2b, q0.y, s3b[1]);
        s3b[2] = ffma2(C2b, q1.x, s3b[2]);
        s3b[3] = ffma2(C2b, q1.y, s3b[3]);
        s3b[4] = ffma2(C2b, q2.x, s3b[4]);
        s3b[5] = ffma2(C2b, q2.y, s3b[5]);
        s3b[6] = ffma2(C2b, q3.x, s3b[6]);
        s3b[7] = ffma2(C2b, q3.y, s3b[7]);
        s3g[0] = ffma2(C2g, q0.x, s3g[0]);
        s3g[1] = ffma2(C2g, q0.y, s3g[1]);
        s3g[2] = ffma2(C2g, q1.x, s3g[2]);
        s3g[3] = ffma2(C2g, q1.y, s3g[3]);
        s3g[4] = ffma2(C2g, q2.x, s3g[4]);
        s3g[5] = ffma2(C2g, q2.y, s3g[5]);
        s3g[6] = ffma2(C2g, q3.x, s3g[6]);
        s3g[7] = ffma2(C2g, q3.y, s3g[7]);
        s3b[0] = ffma2(K3h, v0.x, s3b[0]);
        s3b[1] = ffma2(K3h, v0.y, s3b[1]);
        s3b[2] = ffma2(K3h, v1.x, s3b[2]);
        s3b[3] = ffma2(K3h, v1.y, s3b[3]);
        s3g[0] = ffma2(K3h, v0.x, s3g[0]);
        s3g[1] = ffma2(K3h, v0.y, s3g[1]);
        s3g[2] = ffma2(K3h, v1.x, s3g[2]);
        s3g[3] = ffma2(K3h, v1.y, s3g[3]);
        s3g[4] = ffma2(K36, v0.x, s3g[4]);
        s3g[5] = ffma2(K36, v0.y, s3g[5]);
        s3g[6] = ffma2(K36, v1.x, s3g[6]);
        s3g[7] = ffma2(K36, v1.y, s3g[7]);
        s2b = fmaf(-Da, S1b, fmaf(Da, Db, s2b));
        s2g = fmaf(-Da, S1b8, fmaf(0.5f * Da, Db, s2g));
    }
    s1a -= Da;
}

__device__ __forceinline__ void store_pos(int i, int a, int b,
                                          float* __restrict__ out1,
                                          float* __restrict__ out2,
                                          float* __restrict__ out3,
                                          const u64* s3b, const u64* s3g,
                                          float s2b, float s2g, float s1a)
{
    if (b == 0) out1[i * LLD + a] = s1a;
    const int r2 = i * (LLD * LLD) + a * LLD + b;
    out2[r2]     = s2b;
    out2[r2 + 8] = s2g;

    float* base = out3 + (size_t)i * (LLD * LLD * LLD);
    ulonglong2* ob = reinterpret_cast<ulonglong2*>(base + (a * LLD + b) * LLD);
    ob[0] = make_ulonglong2(s3b[0], s3b[1]);
    ob[1] = make_ulonglong2(s3b[2], s3b[3]);
    ob[2] = make_ulonglong2(s3b[4], s3b[5]);
    ob[3] = make_ulonglong2(s3b[6], s3b[7]);
    ulonglong2* og = reinterpret_cast<ulonglong2*>(base + (a * LLD + b + 8) * LLD);
    og[0] = make_ulonglong2(s3g[0], s3g[1]);
    og[1] = make_ulonglong2(s3g[2], s3g[3]);
    og[2] = make_ulonglong2(s3g[4], s3g[5]);
    og[3] = make_ulonglong2(s3g[6], s3g[7]);
}

__global__ void __launch_bounds__(128, 5)
leadlag_sig_kernel(const float* __restrict__ x,
                   float* __restrict__ out1,
                   float* __restrict__ out2,
                   float* __restrict__ out3,
                   int seq_len)
{
    __shared__ __align__(16) float sd[NDT * DIM];
    __shared__ __align__(16) float s2buf[2][16][20];   // padded rows: conflict-free
    __shared__ __align__(16) float s1buf[2][16];

    const int p0  = blockIdx.x * CHUNK;
    const int tid = threadIdx.x;

    for (int j = tid; j < NDT * DIM; j += 128) {
        int t = j >> 3;
        int c = j & 7;
        int r0 = p0 + t - (PATCH - 1);
        int r1 = r0 + 1;
        float q0 = (r0 >= 0) ? x[r0 * DIM + c] : 0.0f;
        float q1 = (r1 >= 0) ? x[r1 * DIM + c] : 0.0f;
        sd[j] = q1 - q0;
    }
    __syncthreads();

    const int a  = tid >> 3;   // 0..15
    const int b  = tid & 7;    // lead column; lag column is b+8
    const int ai = a & 7;

    u64 s3b[8], s3g[8];
#pragma unroll
    for (int k = 0; k < 8; ++k) { s3b[k] = 0ULL; s3g[k] = 0ULL; }
    float s2b = 0.0f, s2g = 0.0f, s1a = 0.0f;

    // ---- full recursion for position p0 ----
    if (a < 8) {
#pragma unroll
        for (int t = 0; t < NDIFF; ++t)
            right_pair<true>(sd + t * 8, ai, b, s3b, s3g, s2b, s2g, s1a);
    } else {
#pragma unroll
        for (int t = 0; t < NDIFF; ++t)
            right_pair<false>(sd + t * 8, ai, b, s3b, s3g, s2b, s2g, s1a);
    }

    s2buf[0][a][b]     = s2b;
    s2buf[0][a][b + 8] = s2g;
    if (b == 0) s1buf[0][a] = s1a;
    __syncthreads();
    store_pos(p0, a, b, out1, out2, out3, s3b, s3g, s2b, s2g, s1a);

    // ---- slide ----
#pragma unroll 1
    for (int s = 1; s < CHUNK; ++s) {
        const int ob = (s - 1) & 1;
        const int nb = s & 1;
        const float* dOld = sd + (s - 1) * 8;
        const float* dNew = sd + (s + NDIFF - 1) * 8;
        if (a < 8) {
            left_remove<true >(dOld, &s2buf[ob][b][0], &s2buf[ob][b + 8][0],
                               &s1buf[ob][0], ai, b, s3b, s3g, s2b, s2g, s1a);
            right_pair<true >(dNew, ai, b, s3b, s3g, s2b, s2g, s1a);
        } else {
            left_remove<false>(dOld, &s2buf[ob][b][0], &s2buf[ob][b + 8][0],
                               &s1buf[ob][0], ai, b, s3b, s3g, s2b, s2g, s1a);
            right_pair<false>(dNew, ai, b, s3b, s3g, s2b, s2g, s1a);
        }
        s2buf[nb][a][b]     = s2b;
        s2buf[nb][a][b + 8] = s2g;
        if (b == 0) s1buf[nb][a] = s1a;
        __syncthreads();
        store_pos(p0 + s, a, b, out1, out2, out3, s3b, s3g, s2b, s2g, s1a);
    }
}

extern "C" void kernel_launch(void* const* d_in, const int* in_sizes, int n_in,
                              void* d_out, int out_size)
{
    const float* x = (const float*)d_in[0];
    const int seq_len = in_sizes[0] / DIM;

    float* out = (float*)d_out;
    float* out1 = out;
    float* out2 = out + (size_t)seq_len * LLD;
    float* out3 = out + (size_t)seq_len * LLD + (size_t)seq_len * LLD * LLD;

    leadlag_sig_kernel<<<seq_len / CHUNK, 128>>>(x, out1, out2, out3, seq_len);
}

// round 8
// speedup vs baseline: 1.7447x; 1.7447x over previous
#include <cuda_runtime.h>

// LeadLagSignature depth-3, lead-lag of 16-point sliding patches.
// R7 = R3 compute (full 15-step recursion, thread (a,b) owns S2/S3 row a,
// cols b and b+8) + conflict-free smem staging of S3 and coalesced STG.128.

#define DIM 8
#define PATCH 16
#define NDIFF 15
#define LLD 16
#define TSTRIDE 20               // padded row stride in floats (80 B)

typedef unsigned long long u64;

__device__ __forceinline__ u64 ffma2(u64 a, u64 b, u64 c) {
    u64 d;
    asm("fma.rn.f32x2 %0, %1, %2, %3;" : "=l"(d) : "l"(a), "l"(b), "l"(c));
    return d;
}

__device__ __forceinline__ u64 bcast2(float f) {
    unsigned int r = __float_as_uint(f);
    u64 d;
    asm("mov.b64 %0, {%1, %1};" : "=l"(d) : "r"(r));
    return d;
}

// ALEAD: whether row index a is in the lead half (warp-uniform: a = tid>>3
// spans 4 consecutive values per warp, all on one side of 8).
template <bool ALEAD>
__device__ __forceinline__ void sig_loop(const float* __restrict__ sd,
                                         int ai, int bi,
                                         u64* s3b,   // column b   (lead)
                                         u64* s3g,   // column b+8 (lag)
                                         float& s2b, float& s2g, float& s1a) {
    const float C2 = 0.5f;
    const float C3 = 1.0f / 6.0f;
#pragma unroll
    for (int t = 0; t < NDIFF; ++t) {
        const ulonglong2 pA = *reinterpret_cast<const ulonglong2*>(sd + t * 8);
        const ulonglong2 pB = *reinterpret_cast<const ulonglong2*>(sd + t * 8 + 4);
        const float va = sd[t * 8 + ai];
        const float vb = sd[t * 8 + bi];

        float Fb, F2b, Fg, F2g;
        if (ALEAD) {
            // lead step: pa=va; pb: col b -> vb, col b+8 -> 0
            Fg = s2g;
            const float cs1 = C2 * s1a;
            const float u   = fmaf(C3, va, cs1);
            Fb  = fmaf(vb, u, s2b);
            const float w   = fmaf(C2, va, s1a);
            s2b = fmaf(vb, w, s2b);
            s1a += va;
            // lag step: pa=0; pb: col b -> 0, col b+8 -> vb
            F2b = s2b;
            const float h   = C2 * s1a;
            F2g = fmaf(vb, h, s2g);
            s2g = fmaf(vb, s1a, s2g);
        } else {
            // lead step: pa=0
            const float cs1 = C2 * s1a;
            Fb  = fmaf(vb, cs1, s2b);
            s2b = fmaf(vb, s1a, s2b);
            Fg  = s2g;
            // lag step: pa=va
            F2b = s2b;
            const float u   = fmaf(C3, va, cs1);
            F2g = fmaf(vb, u, s2g);
            const float w   = fmaf(C2, va, s1a);
            s2g = fmaf(vb, w, s2g);
            s1a += va;
        }

        const u64 Fbp  = bcast2(Fb);
        const u64 F2bp = bcast2(F2b);
        const u64 Fgp  = bcast2(Fg);
        const u64 F2gp = bcast2(F2g);

        s3b[0] = ffma2(Fbp,  pA.x, s3b[0]);
        s3b[1] = ffma2(Fbp,  pA.y, s3b[1]);
        s3b[2] = ffma2(Fbp,  pB.x, s3b[2]);
        s3b[3] = ffma2(Fbp,  pB.y, s3b[3]);
        s3b[4] = ffma2(F2bp, pA.x, s3b[4]);
        s3b[5] = ffma2(F2bp, pA.y, s3b[5]);
        s3b[6] = ffma2(F2bp, pB.x, s3b[6]);
        s3b[7] = ffma2(F2bp, pB.y, s3b[7]);
        s3g[0] = ffma2(Fgp,  pA.x, s3g[0]);
        s3g[1] = ffma2(Fgp,  pA.y, s3g[1]);
        s3g[2] = ffma2(Fgp,  pB.x, s3g[2]);
        s3g[3] = ffma2(Fgp,  pB.y, s3g[3]);
        s3g[4] = ffma2(F2gp, pA.x, s3g[4]);
        s3g[5] = ffma2(F2gp, pA.y, s3g[5]);
        s3g[6] = ffma2(F2gp, pB.x, s3g[6]);
        s3g[7] = ffma2(F2gp, pB.y, s3g[7]);
    }
}

__global__ void __launch_bounds__(128, 6)
leadlag_sig_kernel(const float* __restrict__ x,
                   float* __restrict__ out1,
                   float* __restrict__ out2,
                   float* __restrict__ out3,
                   int seq_len)
{
    __shared__ __align__(16) float sd[NDIFF * DIM];
    __shared__ __align__(16) float tile[256 * TSTRIDE];   // 20480 B

    const int i   = blockIdx.x;
    const int tid = threadIdx.x;

    if (tid < NDIFF * DIM) {
        int t = tid >> 3;
        int c = tid & 7;
        int r0 = i + t - (PATCH - 1);
        int r1 = r0 + 1;
        float p0 = (r0 >= 0) ? x[r0 * DIM + c] : 0.0f;
        float p1 = (r1 >= 0) ? x[r1 * DIM + c] : 0.0f;
        sd[tid] = p1 - p0;
    }
    __syncthreads();

    const int a  = tid >> 3;        // 0..15
    const int b  = tid & 7;         // lead column; lag column is b+8
    const int ai = a & 7;

    u64 s3b[8], s3g[8];
#pragma unroll
    for (int k = 0; k < 8; ++k) { s3b[k] = 0ULL; s3g[k] = 0ULL; }
    float s2b = 0.0f, s2g = 0.0f, s1a = 0.0f;

    if (a < 8) {   // warp-uniform
        sig_loop<true >(sd, ai, b, s3b, s3g, s2b, s2g, s1a);
    } else {
        sig_loop<false>(sd, ai, b, s3b, s3g, s2b, s2g, s1a);
    }

    // ---- small outputs (direct, cheap) ----
    if (b == 0) out1[i * LLD + a] = s1a;
    const int r2 = i * (LLD * LLD) + a * LLD + b;
    out2[r2]     = s2b;
    out2[r2 + 8] = s2g;

    // ---- stage S3 rows into padded tile (conflict-free: slot = 5b+k mod 8) ----
    const int rb = a * LLD + b;        // logical row of column b
    const int rg = rb + 8;             // logical row of column b+8
    float* tb = tile + rb * TSTRIDE;
    float* tg = tile + rg * TSTRIDE;
#pragma unroll
    for (int k = 0; k < 4; ++k) {
        *reinterpret_cast<ulonglong2*>(tb + k * 4) =
            make_ulonglong2(s3b[2 * k], s3b[2 * k + 1]);
        *reinterpret_cast<ulonglong2*>(tg + k * 4) =
            make_ulonglong2(s3g[2 * k], s3g[2 * k + 1]);
    }
    __syncthreads();

    // ---- coalesced readout: 1024 float4s, lanes consecutive ----
    float* gdst = out3 + (size_t)i * (LLD * LLD * LLD);
#pragma unroll
    for (int it = 0; it < 8; ++it) {
        const int f = it * 128 + tid;       // float4 index 0..1023
        const int r = f >> 2;
        const int q = f & 3;
        const float4 v = *reinterpret_cast<const float4*>(tile + r * TSTRIDE + q * 4);
        *reinterpret_cast<float4*>(gdst + f * 4) = v;
    }
}

extern "C" void kernel_launch(void* const* d_in, const int* in_sizes, int n_in,
                              void* d_out, int out_size)
{
    const float* x = (const float*)d_in[0];
    const int seq_len = in_sizes[0] / DIM;

    float* out = (float*)d_out;
    float* out1 = out;
    float* out2 = out + (size_t)seq_len * LLD;
    float* out3 = out + (size_t)seq_len * LLD + (size_t)seq_len * LLD * LLD;

    leadlag_sig_kernel<<<seq_len, 128>>>(x, out1, out2, out3, seq_len);
}

// round 11
// speedup vs baseline: 2.2503x; 1.2898x over previous
#include <cuda_runtime.h>
#include <cuda.h>

// LeadLagSignature depth-3, lead-lag of 16-point sliding patches.
// R10 = R9 (SW128-swizzled smem staging + single 2D TMA bulk store per position)
// with the tile moved to offset 0 of dynamic smem so the SW128 atom (1024 B)
// phase matches the absolute SMEM address (R9's 128-B static alignment scrambled it).

#define DIM 8
#define PATCH 16
#define NDIFF 15
#define LLD 16
#define TILE_BYTES (LLD * LLD * LLD * 4)          // 16384
#define SMEM_TOTAL (TILE_BYTES + NDIFF * DIM * 4) // + 480 for sd

typedef unsigned long long u64;

__device__ __forceinline__ u64 ffma2(u64 a, u64 b, u64 c) {
    u64 d;
    asm("fma.rn.f32x2 %0, %1, %2, %3;" : "=l"(d) : "l"(a), "l"(b), "l"(c));
    return d;
}

__device__ __forceinline__ u64 bcast2(float f) {
    unsigned int r = __float_as_uint(f);
    u64 d;
    asm("mov.b64 %0, {%1, %1};" : "=l"(d) : "r"(r));
    return d;
}

__device__ __forceinline__ unsigned int smem_u32(const void* p) {
    unsigned int a;
    asm("{ .reg .u64 t; cvta.to.shared.u64 t, %1; cvt.u32.u64 %0, t; }"
        : "=r"(a) : "l"(p));
    return a;
}

// ALEAD: whether row index a is in the lead half (warp-uniform: a = tid>>3
// spans 4 consecutive values per warp, all on one side of 8).
template <bool ALEAD>
__device__ __forceinline__ void sig_loop(const float* __restrict__ sd,
                                         int ai, int bi,
                                         u64* s3b,   // column b   (lead)
                                         u64* s3g,   // column b+8 (lag)
                                         float& s2b, float& s2g, float& s1a) {
    const float C2 = 0.5f;
    const float C3 = 1.0f / 6.0f;
#pragma unroll
    for (int t = 0; t < NDIFF; ++t) {
        const ulonglong2 pA = *reinterpret_cast<const ulonglong2*>(sd + t * 8);
        const ulonglong2 pB = *reinterpret_cast<const ulonglong2*>(sd + t * 8 + 4);
        const float va = sd[t * 8 + ai];
        const float vb = sd[t * 8 + bi];

        float Fb, F2b, Fg, F2g;
        if (ALEAD) {
            Fg = s2g;
            const float cs1 = C2 * s1a;
            const float u   = fmaf(C3, va, cs1);
            Fb  = fmaf(vb, u, s2b);
            const float w   = fmaf(C2, va, s1a);
            s2b = fmaf(vb, w, s2b);
            s1a += va;
            F2b = s2b;
            const float h   = C2 * s1a;
            F2g = fmaf(vb, h, s2g);
            s2g = fmaf(vb, s1a, s2g);
        } else {
            const float cs1 = C2 * s1a;
            Fb  = fmaf(vb, cs1, s2b);
            s2b = fmaf(vb, s1a, s2b);
            Fg  = s2g;
            F2b = s2b;
            const float u   = fmaf(C3, va, cs1);
            F2g = fmaf(vb, u, s2g);
            const float w   = fmaf(C2, va, s1a);
            s2g = fmaf(vb, w, s2g);
            s1a += va;
        }

        const u64 Fbp  = bcast2(Fb);
        const u64 F2bp = bcast2(F2b);
        const u64 Fgp  = bcast2(Fg);
        const u64 F2gp = bcast2(F2g);

        s3b[0] = ffma2(Fbp,  pA.x, s3b[0]);
        s3b[1] = ffma2(Fbp,  pA.y, s3b[1]);
        s3b[2] = ffma2(Fbp,  pB.x, s3b[2]);
        s3b[3] = ffma2(Fbp,  pB.y, s3b[3]);
        s3b[4] = ffma2(F2bp, pA.x, s3b[4]);
        s3b[5] = ffma2(F2bp, pA.y, s3b[5]);
        s3b[6] = ffma2(F2bp, pB.x, s3b[6]);
        s3b[7] = ffma2(F2bp, pB.y, s3b[7]);
        s3g[0] = ffma2(Fgp,  pA.x, s3g[0]);
        s3g[1] = ffma2(Fgp,  pA.y, s3g[1]);
        s3g[2] = ffma2(Fgp,  pB.x, s3g[2]);
        s3g[3] = ffma2(Fgp,  pB.y, s3g[3]);
        s3g[4] = ffma2(F2gp, pA.x, s3g[4]);
        s3g[5] = ffma2(F2gp, pA.y, s3g[5]);
        s3g[6] = ffma2(F2gp, pB.x, s3g[6]);
        s3g[7] = ffma2(F2gp, pB.y, s3g[7]);
    }
}

__device__ __forceinline__ unsigned int sw128(unsigned int byte_off) {
    return byte_off ^ ((byte_off >> 3) & 0x70);
}

__global__ void __launch_bounds__(128, 6)
leadlag_sig_kernel(const float* __restrict__ x,
                   float* __restrict__ out1,
                   float* __restrict__ out2,
                   const __grid_constant__ CUtensorMap tmap,
                   int seq_len)
{
    // Dynamic smem: tile at offset 0 (atom-aligned), sd after it.
    extern __shared__ __align__(16) char dynsmem[];
    float* tile = reinterpret_cast<float*>(dynsmem);            // 16 KB, SW128-swizzled
    float* sd   = reinterpret_cast<float*>(dynsmem + TILE_BYTES);

    const int i   = blockIdx.x;
    const int tid = threadIdx.x;

    if (tid < NDIFF * DIM) {
        int t = tid >> 3;
        int c = tid & 7;
        int r0 = i + t - (PATCH - 1);
        int r1 = r0 + 1;
        float p0 = (r0 >= 0) ? x[r0 * DIM + c] : 0.0f;
        float p1 = (r1 >= 0) ? x[r1 * DIM + c] : 0.0f;
        sd[tid] = p1 - p0;
    }
    __syncthreads();

    const int a  = tid >> 3;        // 0..15
    const int b  = tid & 7;         // lead column; lag column is b+8
    const int ai = a & 7;

    u64 s3b[8], s3g[8];
#pragma unroll
    for (int k = 0; k < 8; ++k) { s3b[k] = 0ULL; s3g[k] = 0ULL; }
    float s2b = 0.0f, s2g = 0.0f, s1a = 0.0f;

    if (a < 8) {   // warp-uniform
        sig_loop<true >(sd, ai, b, s3b, s3g, s2b, s2g, s1a);
    } else {
        sig_loop<false>(sd, ai, b, s3b, s3g, s2b, s2g, s1a);
    }

    // ---- small outputs (direct) ----
    if (b == 0) out1[i * LLD + a] = s1a;
    const int r2 = i * (LLD * LLD) + a * LLD + b;
    out2[r2]     = s2b;
    out2[r2 + 8] = s2g;

    // ---- stage S3 rows into SW128-swizzled tile (conflict-free STS.128) ----
    char* tbytes = reinterpret_cast<char*>(tile);
    const unsigned int rb = (unsigned)(a * LLD + b);   // logical row (16 floats = 64 B)
    const unsigned int rg = rb + 8;
#pragma unroll
    for (int k = 0; k < 4; ++k) {
        const unsigned int ob = sw128(rb * 64u + k * 16u);
        const unsigned int og = sw128(rg * 64u + k * 16u);
        *reinterpret_cast<ulonglong2*>(tbytes + ob) =
            make_ulonglong2(s3b[2 * k], s3b[2 * k + 1]);
        *reinterpret_cast<ulonglong2*>(tbytes + og) =
            make_ulonglong2(s3g[2 * k], s3g[2 * k + 1]);
    }
    __syncthreads();

    // ---- one 2D TMA bulk store: smem tile -> out3[i] (TMA de-swizzles) ----
    if (tid == 0) {
        asm volatile("fence.proxy.async.shared::cta;" ::: "memory");
        const unsigned int src = smem_u32(tile);
        const int cy = i * 128;          // 128 tensor rows (128 B each) per position
        asm volatile(
            "cp.async.bulk.tensor.2d.global.shared::cta.tile.bulk_group "
            "[%0, {%1, %2}], [%3];"
            :: "l"(&tmap), "r"(0), "r"(cy), "r"(src) : "memory");
        asm volatile("cp.async.bulk.commit_group;" ::: "memory");
        asm volatile("cp.async.bulk.wait_group 0;" ::: "memory");
    }
}

// Driver-API entry point resolved through cudart (harness links cudart only).
typedef CUresult (*EncodeTiledFn)(
    CUtensorMap*, CUtensorMapDataType, cuuint32_t, void*,
    const cuuint64_t*, const cuuint64_t*, const cuuint32_t*, const cuuint32_t*,
    CUtensorMapInterleave, CUtensorMapSwizzle, CUtensorMapL2promotion,
    CUtensorMapFloatOOBfill);

extern "C" void kernel_launch(void* const* d_in, const int* in_sizes, int n_in,
                              void* d_out, int out_size)
{
    const float* x = (const float*)d_in[0];
    const int seq_len = in_sizes[0] / DIM;

    float* out = (float*)d_out;
    float* out1 = out;
    float* out2 = out + (size_t)seq_len * LLD;
    float* out3 = out + (size_t)seq_len * LLD + (size_t)seq_len * LLD * LLD;

    void* fn = nullptr;
    cudaDriverEntryPointQueryResult qres = cudaDriverEntryPointSymbolNotFound;
    cudaGetDriverEntryPoint("cuTensorMapEncodeTiled", &fn,
                            cudaEnableDefault, &qres);
    EncodeTiledFn encode = (EncodeTiledFn)fn;

    // 2D view of out3: rows of 32 floats (128 B), seq_len*128 rows total.
    CUtensorMap tmap;
    cuuint64_t dims[2]    = { 32ull, (cuuint64_t)seq_len * 128ull };
    cuuint64_t strides[1] = { 128ull };                 // bytes between rows
    cuuint32_t box[2]     = { 32u, 128u };              // one position = 16 KB tile
    cuuint32_t estr[2]    = { 1u, 1u };
    encode(&tmap, CU_TENSOR_MAP_DATA_TYPE_FLOAT32, 2, (void*)out3,
           dims, strides, box, estr,
           CU_TENSOR_MAP_INTERLEAVE_NONE,
           CU_TENSOR_MAP_SWIZZLE_128B,
           CU_TENSOR_MAP_L2_PROMOTION_L2_128B,
           CU_TENSOR_MAP_FLOAT_OOB_FILL_NONE);

    leadlag_sig_kernel<<<seq_len, 128, SMEM_TOTAL>>>(x, out1, out2, tmap, seq_len);
}

// round 12
// speedup vs baseline: 2.5917x; 1.1517x over previous
#include <cuda_runtime.h>
#include <cuda.h>

// LeadLagSignature depth-3, lead-lag of 16-point sliding patches.
// R11 = R10 (SW128 smem staging + TMA bulk store) x R5 (sliding-window Chen),
// CHUNK=2: full recursion for p0, one left-remove+right-append slide for p0+1,
// double-buffered tiles so the first TMA store overlaps the slide compute.

#define DIM 8
#define PATCH 16
#define NDIFF 15
#define LLD 16
#define NDT 16                                   // diffs needed for 2 positions
#define TILE_BYTES (LLD * LLD * LLD * 4)         // 16384
#define SD_OFF     (2 * TILE_BYTES)              // 32768
#define S2_OFF     (SD_OFF + NDT * DIM * 4)      // +512
#define S1_OFF     (S2_OFF + 16 * 20 * 4)        // +1280
#define SMEM_TOTAL (S1_OFF + 16 * 4)             // 34688

typedef unsigned long long u64;

__device__ __forceinline__ u64 ffma2(u64 a, u64 b, u64 c) {
    u64 d;
    asm("fma.rn.f32x2 %0, %1, %2, %3;" : "=l"(d) : "l"(a), "l"(b), "l"(c));
    return d;
}

__device__ __forceinline__ u64 bcast2(float f) {
    unsigned int r = __float_as_uint(f);
    u64 d;
    asm("mov.b64 %0, {%1, %1};" : "=l"(d) : "r"(r));
    return d;
}

__device__ __forceinline__ unsigned int smem_u32(const void* p) {
    unsigned int a;
    asm("{ .reg .u64 t; cvta.to.shared.u64 t, %1; cvt.u32.u64 %0, t; }"
        : "=r"(a) : "l"(p));
    return a;
}

__device__ __forceinline__ unsigned int sw128(unsigned int byte_off) {
    return byte_off ^ ((byte_off >> 3) & 0x70);
}

// ---- right-append of the two increments (lead then lag) of diff vector dv ----
template <bool ALEAD>
__device__ __forceinline__ void right_pair(const float* __restrict__ dv,
                                           int ai, int bi,
                                           u64* s3b, u64* s3g,
                                           float& s2b, float& s2g, float& s1a)
{
    const float C2 = 0.5f;
    const float C3 = 1.0f / 6.0f;
    const ulonglong2 pA = *reinterpret_cast<const ulonglong2*>(dv);
    const ulonglong2 pB = *reinterpret_cast<const ulonglong2*>(dv + 4);
    const float va = dv[ai];
    const float vb = dv[bi];

    float Fb, F2b, Fg, F2g;
    if (ALEAD) {
        Fg = s2g;
        const float cs1 = C2 * s1a;
        const float u   = fmaf(C3, va, cs1);
        Fb  = fmaf(vb, u, s2b);
        const float w   = fmaf(C2, va, s1a);
        s2b = fmaf(vb, w, s2b);
        s1a += va;
        F2b = s2b;
        const float h   = C2 * s1a;
        F2g = fmaf(vb, h, s2g);
        s2g = fmaf(vb, s1a, s2g);
    } else {
        const float cs1 = C2 * s1a;
        Fb  = fmaf(vb, cs1, s2b);
        s2b = fmaf(vb, s1a, s2b);
        Fg  = s2g;
        F2b = s2b;
        const float u   = fmaf(C3, va, cs1);
        F2g = fmaf(vb, u, s2g);
        const float w   = fmaf(C2, va, s1a);
        s2g = fmaf(vb, w, s2g);
        s1a += va;
    }

    const u64 Fbp  = bcast2(Fb);
    const u64 F2bp = bcast2(F2b);
    const u64 Fgp  = bcast2(Fg);
    const u64 F2gp = bcast2(F2g);

    s3b[0] = ffma2(Fbp,  pA.x, s3b[0]);
    s3b[1] = ffma2(Fbp,  pA.y, s3b[1]);
    s3b[2] = ffma2(Fbp,  pB.x, s3b[2]);
    s3b[3] = ffma2(Fbp,  pB.y, s3b[3]);
    s3b[4] = ffma2(F2bp, pA.x, s3b[4]);
    s3b[5] = ffma2(F2bp, pA.y, s3b[5]);
    s3b[6] = ffma2(F2bp, pB.x, s3b[6]);
    s3b[7] = ffma2(F2bp, pB.y, s3b[7]);
    s3g[0] = ffma2(Fgp,  pA.x, s3g[0]);
    s3g[1] = ffma2(Fgp,  pA.y, s3g[1]);
    s3g[2] = ffma2(Fgp,  pB.x, s3g[2]);
    s3g[3] = ffma2(Fgp,  pB.y, s3g[3]);
    s3g[4] = ffma2(F2gp, pA.x, s3g[4]);
    s3g[5] = ffma2(F2gp, pA.y, s3g[5]);
    s3g[6] = ffma2(F2gp, pB.x, s3g[6]);
    s3g[7] = ffma2(F2gp, pB.y, s3g[7]);
}

// ---- combined left-removal by C = e^{-G(d)} ⊗ e^{-L(d)} (verified in R5) ----
template <bool ALEAD>
__device__ __forceinline__ void left_remove(const float* __restrict__ dOld,
                                            const float* __restrict__ s2rowb,
                                            const float* __restrict__ s2rowg,
                                            const float* __restrict__ s1old,
                                            int ai, int b,
                                            u64* s3b, u64* s3g,
                                            float& s2b, float& s2g, float& s1a)
{
    const float Da = dOld[ai];
    const float Db = dOld[b];
    const ulonglong2 v0 = *reinterpret_cast<const ulonglong2*>(dOld);
    const ulonglong2 v1 = *reinterpret_cast<const ulonglong2*>(dOld + 4);
    const u64 C1 = bcast2(-Da);
    const float t = Da * Db;

    const ulonglong2 q0 = *reinterpret_cast<const ulonglong2*>(s1old);
    const ulonglong2 q1 = *reinterpret_cast<const ulonglong2*>(s1old + 4);
    const ulonglong2 q2 = *reinterpret_cast<const ulonglong2*>(s1old + 8);
    const ulonglong2 q3 = *reinterpret_cast<const ulonglong2*>(s1old + 12);
    const float S1b  = s1old[b];
    const float S1b8 = s1old[b + 8];

    const ulonglong2 rb0 = *reinterpret_cast<const ulonglong2*>(s2rowb);
    const ulonglong2 rb1 = *reinterpret_cast<const ulonglong2*>(s2rowb + 4);
    const ulonglong2 rb2 = *reinterpret_cast<const ulonglong2*>(s2rowb + 8);
    const ulonglong2 rb3 = *reinterpret_cast<const ulonglong2*>(s2rowb + 12);
    const ulonglong2 rg0 = *reinterpret_cast<const ulonglong2*>(s2rowg);
    const ulonglong2 rg1 = *reinterpret_cast<const ulonglong2*>(s2rowg + 4);
    const ulonglong2 rg2 = *reinterpret_cast<const ulonglong2*>(s2rowg + 8);
    const ulonglong2 rg3 = *reinterpret_cast<const ulonglong2*>(s2rowg + 12);

    s3b[0] = ffma2(C1, rb0.x, s3b[0]);
    s3b[1] = ffma2(C1, rb0.y, s3b[1]);
    s3b[2] = ffma2(C1, rb1.x, s3b[2]);
    s3b[3] = ffma2(C1, rb1.y, s3b[3]);
    s3b[4] = ffma2(C1, rb2.x, s3b[4]);
    s3b[5] = ffma2(C1, rb2.y, s3b[5]);
    s3b[6] = ffma2(C1, rb3.x, s3b[6]);
    s3b[7] = ffma2(C1, rb3.y, s3b[7]);
    s3g[0] = ffma2(C1, rg0.x, s3g[0]);
    s3g[1] = ffma2(C1, rg0.y, s3g[1]);
    s3g[2] = ffma2(C1, rg1.x, s3g[2]);
    s3g[3] = ffma2(C1, rg1.y, s3g[3]);
    s3g[4] = ffma2(C1, rg2.x, s3g[4]);
    s3g[5] = ffma2(C1, rg2.y, s3g[5]);
    s3g[6] = ffma2(C1, rg3.x, s3g[6]);
    s3g[7] = ffma2(C1, rg3.y, s3g[7]);

    if (ALEAD) {
        const u64 C2b = bcast2(0.5f * t);
        const u64 K3l = bcast2(-t * (1.0f / 6.0f));
        s3b[0] = ffma2(C2b, q0.x, s3b[0]);
        s3b[1] = ffma2(C2b, q0.y, s3b[1]);
        s3b[2] = ffma2(C2b, q1.x, s3b[2]);
        s3b[3] = ffma2(C2b, q1.y, s3b[3]);
        s3b[4] = ffma2(C2b, q2.x, s3b[4]);
        s3b[5] = ffma2(C2b, q2.y, s3b[5]);
        s3b[6] = ffma2(C2b, q3.x, s3b[6]);
        s3b[7] = ffma2(C2b, q3.y, s3b[7]);
        s3b[0] = ffma2(K3l, v0.x, s3b[0]);
        s3b[1] = ffma2(K3l, v0.y, s3b[1]);
        s3b[2] = ffma2(K3l, v1.x, s3b[2]);
        s3b[3] = ffma2(K3l, v1.y, s3b[3]);
        s2b = fmaf(-Da, S1b, fmaf(0.5f * Da, Db, s2b));
        s2g = fmaf(-Da, S1b8, s2g);
    } else {
        const u64 C2b = bcast2(t);
        const u64 C2g = bcast2(0.5f * t);
        const u64 K3h = bcast2(-0.5f * t);
        const u64 K36 = bcast2(-t * (1.0f / 6.0f));
        s3b[0] = ffma2(C2b, q0.x, s3b[0]);
        s3b[1] = ffma2(C2b, q0.y, s3b[1]);
        s3b[2] = ffma2(C2b, q1.x, s3b[2]);
        s3b[3] = ffma2(C2b, q1.y, s3b[3]);
        s3b[4] = ffma2(C2b, q2.x, s3b[4]);
        s3b[5] = ffma2(C2b, q2.y, s3b[5]);
        s3b[6] = ffma2(C2b, q3.x, s3b[6]);
        s3b[7] = ffma2(C2b, q3.y, s3b[7]);
        s3g[0] = ffma2(C2g, q0.x, s3g[0]);
        s3g[1] = ffma2(C2g, q0.y, s3g[1]);
        s3g[2] = ffma2(C2g, q1.x, s3g[2]);
        s3g[3] = ffma2(C2g, q1.y, s3g[3]);
        s3g[4] = ffma2(C2g, q2.x, s3g[4]);
        s3g[5] = ffma2(C2g, q2.y, s3g[5]);
        s3g[6] = ffma2(C2g, q3.x, s3g[6]);
        s3g[7] = ffma2(C2g, q3.y, s3g[7]);
        s3b[0] = ffma2(K3h, v0.x, s3b[0]);
        s3b[1] = ffma2(K3h, v0.y, s3b[1]);
        s3b[2] = ffma2(K3h, v1.x, s3b[2]);
        s3b[3] = ffma2(K3h, v1.y, s3b[3]);
        s3g[0] = ffma2(K3h, v0.x, s3g[0]);
        s3g[1] = ffma2(K3h, v0.y, s3g[1]);
        s3g[2] = ffma2(K3h, v1.x, s3g[2]);
        s3g[3] = ffma2(K3h, v1.y, s3g[3]);
        s3g[4] = ffma2(K36, v0.x, s3g[4]);
        s3g[5] = ffma2(K36, v0.y, s3g[5]);
        s3g[6] = ffma2(K36, v1.x, s3g[6]);
        s3g[7] = ffma2(K36, v1.y, s3g[7]);
        s2b = fmaf(-Da, S1b, fmaf(Da, Db, s2b));
        s2g = fmaf(-Da, S1b8, fmaf(0.5f * Da, Db, s2g));
    }
    s1a -= Da;
}

// Stage this thread's two S3 rows into a SW128-swizzled tile (conflict-free).
__device__ __forceinline__ void stage_tile(char* __restrict__ tbytes,
                                           int a, int b,
                                           const u64* s3b, const u64* s3g)
{
    const unsigned int rb = (unsigned)(a * LLD + b);
    const unsigned int rg = rb + 8;
#pragma unroll
    for (int k = 0; k < 4; ++k) {
        const unsigned int ob = sw128(rb * 64u + k * 16u);
        const unsigned int og = sw128(rg * 64u + k * 16u);
        *reinterpret_cast<ulonglong2*>(tbytes + ob) =
            make_ulonglong2(s3b[2 * k], s3b[2 * k + 1]);
        *reinterpret_cast<ulonglong2*>(tbytes + og) =
            make_ulonglong2(s3g[2 * k], s3g[2 * k + 1]);
    }
}

__global__ void __launch_bounds__(128, 5)
leadlag_sig_kernel(const float* __restrict__ x,
                   float* __restrict__ out1,
                   float* __restrict__ out2,
                   const __grid_constant__ CUtensorMap tmap,
                   int seq_len)
{
    extern __shared__ __align__(16) char dynsmem[];
    char*  tile0 = dynsmem;                                  // SW128 tiles, atom-aligned
    char*  tile1 = dynsmem + TILE_BYTES;
    float* sd    = reinterpret_cast<float*>(dynsmem + SD_OFF);
    float* s2buf = reinterpret_cast<float*>(dynsmem + S2_OFF);   // 16 rows x 20 floats
    float* s1buf = reinterpret_cast<float*>(dynsmem + S1_OFF);   // 16 floats

    const int p0  = blockIdx.x * 2;
    const int tid = threadIdx.x;

    // 16 diffs: diff t uses x rows (p0 + t - 15, p0 + t - 14)
    {
        int t = tid >> 3;
        int c = tid & 7;
        int r0 = p0 + t - (PATCH - 1);
        int r1 = r0 + 1;
        float q0 = (r0 >= 0) ? x[r0 * DIM + c] : 0.0f;
        float q1 = (r1 >= 0) ? x[r1 * DIM + c] : 0.0f;
        sd[tid] = q1 - q0;
    }
    __syncthreads();

    const int a  = tid >> 3;   // 0..15
    const int b  = tid & 7;    // lead column; lag column is b+8
    const int ai = a & 7;

    u64 s3b[8], s3g[8];
#pragma unroll
    for (int k = 0; k < 8; ++k) { s3b[k] = 0ULL; s3g[k] = 0ULL; }
    float s2b = 0.0f, s2g = 0.0f, s1a = 0.0f;

    // ---- full recursion for position p0 (diffs 0..14) ----
    if (a < 8) {
#pragma unroll
        for (int t = 0; t < NDIFF; ++t)
            right_pair<true>(sd + t * 8, ai, b, s3b, s3g, s2b, s2g, s1a);
    } else {
#pragma unroll
        for (int t = 0; t < NDIFF; ++t)
            right_pair<false>(sd + t * 8, ai, b, s3b, s3g, s2b, s2g, s1a);
    }

    // hand off S2/S1 state for the slide
    s2buf[a * 20 + b]     = s2b;
    s2buf[a * 20 + b + 8] = s2g;
    if (b == 0) s1buf[a] = s1a;

    // small outputs pos0
    if (b == 0) out1[p0 * LLD + a] = s1a;
    {
        const int r2 = p0 * (LLD * LLD) + a * LLD + b;
        out2[r2]     = s2b;
        out2[r2 + 8] = s2g;
    }

    stage_tile(tile0, a, b, s3b, s3g);
    __syncthreads();

    // launch pos0 TMA store (no wait — overlaps the slide compute)
    if (tid == 0) {
        asm volatile("fence.proxy.async.shared::cta;" ::: "memory");
        const unsigned int src = smem_u32(tile0);
        const int cy = p0 * 128;
        asm volatile(
            "cp.async.bulk.tensor.2d.global.shared::cta.tile.bulk_group "
            "[%0, {%1, %2}], [%3];"
            :: "l"(&tmap), "r"(0), "r"(cy), "r"(src) : "memory");
        asm volatile("cp.async.bulk.commit_group;" ::: "memory");
    }

    // ---- slide to pos p0+1: remove diff 0, append diff 15 ----
    if (a < 8) {
        left_remove<true >(sd, s2buf + b * 20, s2buf + (b + 8) * 20,
                           s1buf, ai, b, s3b, s3g, s2b, s2g, s1a);
        right_pair<true >(sd + NDIFF * 8, ai, b, s3b, s3g, s2b, s2g, s1a);
    } else {
        left_remove<false>(sd, s2buf + b * 20, s2buf + (b + 8) * 20,
                           s1buf, ai, b, s3b, s3g, s2b, s2g, s1a);
        right_pair<false>(sd + NDIFF * 8, ai, b, s3b, s3g, s2b, s2g, s1a);
    }

    // small outputs pos1
    const int p1 = p0 + 1;
    if (b == 0) out1[p1 * LLD + a] = s1a;
    {
        const int r2 = p1 * (LLD * LLD) + a * LLD + b;
        out2[r2]     = s2b;
        out2[r2 + 8] = s2g;
    }

    stage_tile(tile1, a, b, s3b, s3g);
    __syncthreads();

    if (tid == 0) {
        asm volatile("fence.proxy.async.shared::cta;" ::: "memory");
        const unsigned int src = smem_u32(tile1);
        const int cy = p1 * 128;
        asm volatile(
            "cp.async.bulk.tensor.2d.global.shared::cta.tile.bulk_group "
            "[%0, {%1, %2}], [%3];"
            :: "l"(&tmap), "r"(0), "r"(cy), "r"(src) : "memory");
        asm volatile("cp.async.bulk.commit_group;" ::: "memory");
        asm volatile("cp.async.bulk.wait_group 0;" ::: "memory");
    }
}

// Driver-API entry point resolved through cudart (harness links cudart only).
typedef CUresult (*EncodeTiledFn)(
    CUtensorMap*, CUtensorMapDataType, cuuint32_t, void*,
    const cuuint64_t*, const cuuint64_t*, const cuuint32_t*, const cuuint32_t*,
    CUtensorMapInterleave, CUtensorMapSwizzle, CUtensorMapL2promotion,
    CUtensorMapFloatOOBfill);

extern "C" void kernel_launch(void* const* d_in, const int* in_sizes, int n_in,
                              void* d_out, int out_size)
{
    const float* x = (const float*)d_in[0];
    const int seq_len = in_sizes[0] / DIM;

    float* out = (float*)d_out;
    float* out1 = out;
    float* out2 = out + (size_t)seq_len * LLD;
    float* out3 = out + (size_t)seq_len * LLD + (size_t)seq_len * LLD * LLD;

    void* fn = nullptr;
    cudaDriverEntryPointQueryResult qres = cudaDriverEntryPointSymbolNotFound;
    cudaGetDriverEntryPoint("cuTensorMapEncodeTiled", &fn,
                            cudaEnableDefault, &qres);
    EncodeTiledFn encode = (EncodeTiledFn)fn;

    // 2D view of out3: rows of 32 floats (128 B), seq_len*128 rows total.
    CUtensorMap tmap;
    cuuint64_t dims[2]    = { 32ull, (cuuint64_t)seq_len * 128ull };
    cuuint64_t strides[1] = { 128ull };
    cuuint32_t box[2]     = { 32u, 128u };
    cuuint32_t estr[2]    = { 1u, 1u };
    encode(&tmap, CU_TENSOR_MAP_DATA_TYPE_FLOAT32, 2, (void*)out3,
           dims, strides, box, estr,
           CU_TENSOR_MAP_INTERLEAVE_NONE,
           CU_TENSOR_MAP_SWIZZLE_128B,
           CU_TENSOR_MAP_L2_PROMOTION_L2_128B,
           CU_TENSOR_MAP_FLOAT_OOB_FILL_NONE);

    leadlag_sig_kernel<<<seq_len / 2, 128, SMEM_TOTAL>>>(x, out1, out2, tmap, seq_len);
}